// round 13
// baseline (speedup 1.0000x reference)
#include <cuda_runtime.h>
#include <cuda_bf16.h>

#define EMSG  131072
#define NNODE 8192
#define DDIM  256
#define NB    512
#define PCAP  64
#define TM    128
#define SST   8
#define NTILE (NNODE/TM)
#define PB    264
#define PA    136

// k_mma dynamic smem layout (bytes)
#define OFF_AH 0
#define OFF_AL 17408
#define OFF_BH 34816
#define OFF_BL 68608
#define SMEM_SZ 102400
#define BBUF   16896   // per-buffer B bytes (16*PB*4)

typedef unsigned long long u64;

__device__ int   g_counts [NNODE];
__device__ int   g_offsets[NNODE];
__device__ int   g_cursor [NNODE];
__device__ int   g_ids    [EMSG];
__device__ float g_tk     [EMSG];
__device__ int   g_order  [NNODE];
__device__ int   g_kbins  [NB];
__device__ int   g_koff   [NB];
__device__ int   g_kcur   [NB];
__device__ int   g_pmax;
__device__ int   g_gidx   [PCAP * NNODE];
__device__ int   g_nodeOf [NNODE];
__device__ int   g_Kof    [NNODE];
__device__ __align__(16) float    g_Wp [PCAP][DDIM*DDIM];   // (W^p)^T fp32
__device__ __align__(16) unsigned g_WH [PCAP][128*DDIM];    // bf16x2 hi (k-pair packed)
__device__ __align__(16) unsigned g_WL [PCAP][128*DDIM];    // bf16x2 lo
__device__ __align__(16) float    g_v  [PCAP][DDIM];
__device__ __align__(16) float    g_cb [PCAP+1][DDIM];
__device__ __align__(16) float    g_part[SST * NNODE * DDIM];

__device__ __forceinline__ void split2(float x0, float x1, unsigned& hi, unsigned& lo) {
    __nv_bfloat16 h0 = __float2bfloat16(x0);
    __nv_bfloat16 h1 = __float2bfloat16(x1);
    float r0 = x0 - __bfloat162float(h0);
    float r1 = x1 - __bfloat162float(h1);
    __nv_bfloat162 H; H.x = h0; H.y = h1;
    __nv_bfloat162 L = __floats2bfloat162_rn(r0, r1);
    hi = *(unsigned*)&H; lo = *(unsigned*)&L;
}

#define MMA_BF16(c, A0, A1, A2, A3, B0, B1) \
    asm volatile("mma.sync.aligned.m16n8k16.row.col.f32.bf16.bf16.f32 " \
        "{%0,%1,%2,%3}, {%4,%5,%6,%7}, {%8,%9}, {%0,%1,%2,%3};" \
        : "+f"(c[0]), "+f"(c[1]), "+f"(c[2]), "+f"(c[3]) \
        : "r"(A0), "r"(A1), "r"(A2), "r"(A3), "r"(B0), "r"(B1))

static __device__ __forceinline__ unsigned smem_u32(const void* p) {
    unsigned a;
    asm("{ .reg .u64 t; cvta.to.shared.u64 t, %1; cvt.u32.u64 %0, t; }" : "=r"(a) : "l"(p));
    return a;
}

// ---------------- setup ----------------
__global__ void k_init() {
    int i = blockIdx.x * blockDim.x + threadIdx.x;
    if (i < NNODE) { g_counts[i] = 0; g_cursor[i] = 0; }
    if (i < NB)    { g_kbins[i]  = 0; g_kcur[i]   = 0; }
    if (i == 0)    g_pmax = 0;
}
__global__ void k_hist(const int* __restrict__ idx) {
    int e = blockIdx.x * blockDim.x + threadIdx.x;
    if (e < EMSG) atomicAdd(&g_counts[idx[e]], 1);
}
__global__ void k_pmax() {
    __shared__ int sm_;
    if (threadIdx.x == 0) sm_ = 0;
    __syncthreads();
    int n = blockIdx.x * blockDim.x + threadIdx.x;
    int v = (n < NNODE) ? min(g_counts[n], PCAP) : 0;
#pragma unroll
    for (int o = 16; o > 0; o >>= 1) v = max(v, __shfl_down_sync(~0u, v, o));
    if ((threadIdx.x & 31) == 0) atomicMax(&sm_, v);
    __syncthreads();
    if (threadIdx.x == 0) atomicMax(&g_pmax, sm_);
}
__global__ void k_scan() {
    __shared__ int part[1024];
    int tid = threadIdx.x, base = tid * 8;
    int loc[8]; int s = 0;
#pragma unroll
    for (int j = 0; j < 8; j++) { loc[j] = g_counts[base + j]; s += loc[j]; }
    part[tid] = s; __syncthreads();
    for (int off = 1; off < 1024; off <<= 1) {
        int v = (tid >= off) ? part[tid - off] : 0;
        __syncthreads(); part[tid] += v; __syncthreads();
    }
    int run = (tid > 0) ? part[tid - 1] : 0;
#pragma unroll
    for (int j = 0; j < 8; j++) { g_offsets[base + j] = run; run += loc[j]; }
}
__global__ void k_scatter(const int* __restrict__ idx, const float* __restrict__ t) {
    int e = blockIdx.x * blockDim.x + threadIdx.x;
    if (e < EMSG) {
        int n = idx[e];
        int p = atomicAdd(&g_cursor[n], 1);
        int slot = g_offsets[n] + p;
        g_ids[slot] = e; g_tk[slot] = t[e];
    }
}
__global__ void k_kbhist() {
    int n = blockIdx.x * blockDim.x + threadIdx.x;
    if (n < NNODE) atomicAdd(&g_kbins[min(g_counts[n], NB - 1)], 1);
}
__global__ void k_kscan() {
    __shared__ int part[NB];
    int tid = threadIdx.x;
    part[tid] = g_kbins[tid]; __syncthreads();
    for (int off = 1; off < NB; off <<= 1) {
        int v = (tid >= off) ? part[tid - off] : 0;
        __syncthreads(); part[tid] += v; __syncthreads();
    }
    g_koff[tid] = (tid > 0) ? part[tid - 1] : 0;
}
__global__ void k_korder() {
    int n = blockIdx.x * blockDim.x + threadIdx.x;
    if (n < NNODE) {
        int kb = min(g_counts[n], NB - 1);
        int p = atomicAdd(&g_kcur[kb], 1);
        g_order[g_koff[kb] + p] = n;
    }
}
__global__ void k_sortgidx() {
    int wg  = (blockIdx.x * blockDim.x + threadIdx.x) >> 5;
    int lane = threadIdx.x & 31;
    if (wg >= NNODE) return;
    int j = wg;
    int n = g_order[NNODE - 1 - j];
    int K = g_counts[n], off = g_offsets[n];
    int Kc = min(K, PCAP);
    if (lane == 0) { g_nodeOf[j] = n; g_Kof[j] = Kc; }
    u64 v0 = ~0ull, v1 = ~0ull;
    if (lane < K)
        v0 = (((u64)__float_as_uint(g_tk[off + lane])) << 32) | (unsigned)g_ids[off + lane];
    if (lane + 32 < K)
        v1 = (((u64)__float_as_uint(g_tk[off + lane + 32])) << 32) | (unsigned)g_ids[off + lane + 32];
#pragma unroll
    for (int k = 2; k <= 64; k <<= 1) {
#pragma unroll
        for (int jj = k >> 1; jj > 0; jj >>= 1) {
            if (jj == 32) {
                u64 lo = v0 < v1 ? v0 : v1;
                u64 hi = v0 < v1 ? v1 : v0;
                v0 = lo; v1 = hi;
            } else {
                u64 p0 = __shfl_xor_sync(0xffffffffu, v0, jj);
                u64 p1 = __shfl_xor_sync(0xffffffffu, v1, jj);
                bool up  = (lane & jj) == 0;
                bool as0 = (lane & k) == 0;
                bool as1 = ((lane + 32) & k) == 0;
                v0 = (as0 == up) ? (v0 < p0 ? v0 : p0) : (v0 < p0 ? p0 : v0);
                v1 = (as1 == up) ? (v1 < p1 ? v1 : p1) : (v1 < p1 ? p1 : v1);
            }
        }
    }
    if (lane < Kc)
        g_gidx[(Kc - lane - 1) * NNODE + j] = (int)(unsigned)(v0 & 0xffffffffull);
    if (lane + 32 < Kc)
        g_gidx[(Kc - lane - 33) * NNODE + j] = (int)(unsigned)(v1 & 0xffffffffull);
}
__global__ void k_transpose(const float* __restrict__ W) {
    int i = blockIdx.x * blockDim.x + threadIdx.x;
    int k = i >> 8, jj = i & 255;
    g_Wp[0][k * DDIM + jj] = W[jj * DDIM + k];
}

// W powers: 64x64 tile, 4x4 per thread. C = (W^{half+r})^T = (W^r)^T @ (W^half)^T
__global__ void __launch_bounds__(256) k_wpow(int half) {
    int r = blockIdx.y + 1, p = half + r;
    if (p > PCAP || p > g_pmax) return;
    const float4* P4 = (const float4*)g_Wp[r - 1];
    const float4* Q4 = (const float4*)g_Wp[half - 1];
    float* C = g_Wp[p - 1];
    int row0 = (blockIdx.x & 3) * 64;
    int col0 = (blockIdx.x >> 2) * 64;

    __shared__ __align__(16) float sPT[16 * 68];   // [kk][row]
    __shared__ __align__(16) float sQ [16 * 68];   // [kk][col]

    int tid = threadIdx.x;
    int ty = tid >> 4, tx = tid & 15;
    int pr = tid >> 2, pq = tid & 3;     // P: row, k-quad
    int qk = tid >> 4, qc = tid & 15;    // Q: k-row, col-quad
    float acc[4][4] = {};

    for (int kc = 0; kc < DDIM; kc += 16) {
        float4 pv = P4[(row0 + pr) * 64 + (kc >> 2) + pq];
        float4 qv = Q4[(kc + qk) * 64 + (col0 >> 2) + qc];
        __syncthreads();
        sPT[(pq * 4 + 0) * 68 + pr] = pv.x;
        sPT[(pq * 4 + 1) * 68 + pr] = pv.y;
        sPT[(pq * 4 + 2) * 68 + pr] = pv.z;
        sPT[(pq * 4 + 3) * 68 + pr] = pv.w;
        *(float4*)&sQ[qk * 68 + qc * 4] = qv;
        __syncthreads();
#pragma unroll
        for (int kk = 0; kk < 16; kk++) {
            float4 a = *(float4*)&sPT[kk * 68 + ty * 4];
            float4 b = *(float4*)&sQ[kk * 68 + tx * 4];
            float ar[4] = {a.x, a.y, a.z, a.w};
            float br[4] = {b.x, b.y, b.z, b.w};
#pragma unroll
            for (int i = 0; i < 4; i++)
#pragma unroll
                for (int j = 0; j < 4; j++)
                    acc[i][j] += ar[i] * br[j];
        }
    }
#pragma unroll
    for (int i = 0; i < 4; i++)
        *(float4*)&C[(row0 + ty * 4 + i) * DDIM + col0 + tx * 4] =
            make_float4(acc[i][0], acc[i][1], acc[i][2], acc[i][3]);
}

// bf16 hi/lo k-pair packed: g_WH[p][pair*256+j] = {Wt[2k][j], Wt[2k+1][j]}
__global__ void k_wsplit() {
    int p = blockIdx.y;
    if (p >= g_pmax) return;
    int i = blockIdx.x * 256 + threadIdx.x;
    int pair = i >> 8, jj = i & 255;
    const float* Wt = g_Wp[p];
    float x0 = Wt[(2 * pair) * DDIM + jj];
    float x1 = Wt[(2 * pair + 1) * DDIM + jj];
    unsigned h, l; split2(x0, x1, h, l);
    g_WH[p][pair * DDIM + jj] = h;
    g_WL[p][pair * DDIM + jj] = l;
}
__global__ void k_vj(const float* __restrict__ b) {
    int jj = blockIdx.x + 1;
    if (jj >= g_pmax) return;
    __shared__ float sb[DDIM];
    sb[threadIdx.x] = b[threadIdx.x];
    __syncthreads();
    const float* Wt = g_Wp[jj - 1];
    int i = threadIdx.x;
    float s = 0.f;
#pragma unroll 8
    for (int k = 0; k < DDIM; k++) s += Wt[k * DDIM + i] * sb[k];
    g_v[jj][i] = s;
}
__global__ void k_cbias(const float* __restrict__ b) {
    int i = threadIdx.x;
    float run = 0.f;
    g_cb[0][i] = 0.f;
    for (int K = 1; K <= PCAP; K++) {
        run += (K == 1) ? b[i] : g_v[K - 1][i];
        g_cb[K][i] = run;
    }
}

// ---------------- main tensor-core kernel: cp.async double-buffered ----------------
__global__ void __launch_bounds__(512, 1) k_mma(const float* __restrict__ msg) {
    extern __shared__ __align__(16) char sm[];
    int T = blockIdx.x >> 3, s = blockIdx.x & 7;
    int tid = threadIdx.x;
    int w = tid >> 5, l = tid & 31;
    int g = l >> 2, t = l & 3;
    int wr = w & 3, wc = w >> 2;
    int Kmax = g_Kof[T * TM];
    int nP = (Kmax >= s + 1) ? ((Kmax - (s + 1)) / SST + 1) : 0;
    int C = nP * 8;

    unsigned bhB0 = smem_u32(sm + OFF_BH);
    unsigned blB0 = smem_u32(sm + OFF_BL);

    float acc[2][8][4];
#pragma unroll
    for (int a = 0; a < 2; a++)
#pragma unroll
        for (int c = 0; c < 8; c++)
#pragma unroll
            for (int q = 0; q < 4; q++) acc[a][c][q] = 0.f;

    const float4* msg4 = (const float4*)msg;
    int arow = tid >> 2, aq = tid & 3;
    int grow = T * TM + arow;
    int kof = g_Kof[grow];

    float4 pav[2][2];

#define LOADA(n) do { int st_ = (n) & 1; \
    int p_ = s + 1 + ((n) >> 3) * SST, kc_ = (n) & 7; \
    int aid_ = (p_ <= kof) ? g_gidx[(p_ - 1) * NNODE + grow] : -1; \
    pav[st_][0] = make_float4(0.f, 0.f, 0.f, 0.f); pav[st_][1] = pav[st_][0]; \
    if (aid_ >= 0) { \
        pav[st_][0] = msg4[(size_t)aid_ * 64 + kc_ * 8 + aq]; \
        pav[st_][1] = msg4[(size_t)aid_ * 64 + kc_ * 8 + aq + 4]; \
    } \
} while (0)

#define STOREA(n) do { int b_ = (n) & 1; \
    unsigned* aH_ = (unsigned*)(sm + OFF_AH) + b_ * (16 * PA); \
    unsigned* aL_ = (unsigned*)(sm + OFF_AL) + b_ * (16 * PA); \
    _Pragma("unroll") \
    for (int u = 0; u < 2; u++) { \
        int f = aq + u * 4; \
        unsigned h0, l0, h1, l1; \
        split2(pav[b_][u].x, pav[b_][u].y, h0, l0); \
        split2(pav[b_][u].z, pav[b_][u].w, h1, l1); \
        aH_[(2 * f + 0) * PA + arow] = h0; aH_[(2 * f + 1) * PA + arow] = h1; \
        aL_[(2 * f + 0) * PA + arow] = l0; aL_[(2 * f + 1) * PA + arow] = l1; \
    } \
} while (0)

#define CPB(n) do { int b_ = (n) & 1; \
    int p_ = s + 1 + ((n) >> 3) * SST, kc_ = (n) & 7; \
    const unsigned* WH_ = g_WH[p_ - 1] + kc_ * 4096; \
    const unsigned* WL_ = g_WL[p_ - 1] + kc_ * 4096; \
    _Pragma("unroll") \
    for (int u = 0; u < 2; u++) { \
        int f = u * 512 + tid; int pr_ = f >> 6, j4_ = f & 63; \
        unsigned off_ = (unsigned)(pr_ * PB + j4_ * 4) * 4; \
        asm volatile("cp.async.cg.shared.global [%0], [%1], 16;" \
            :: "r"(bhB0 + b_ * BBUF + off_), "l"(WH_ + pr_ * 256 + j4_ * 4)); \
        asm volatile("cp.async.cg.shared.global [%0], [%1], 16;" \
            :: "r"(blB0 + b_ * BBUF + off_), "l"(WL_ + pr_ * 256 + j4_ * 4)); \
    } \
    asm volatile("cp.async.commit_group;" ::: "memory"); \
} while (0)

#define WAITB() asm volatile("cp.async.wait_group 0;" ::: "memory")

    if (C > 0) {
        LOADA(0);
        CPB(0);
        if (C > 1) LOADA(1);
        WAITB();
        STOREA(0);
        __syncthreads();

        for (int c = 0; c < C; c++) {
            if (c + 1 < C) CPB(c + 1);
            if (c + 1 < C) STOREA(c + 1);
            if (c + 2 < C) LOADA(c + 2);

            int buf = c & 1;
            const unsigned* aHb = (const unsigned*)(sm + OFF_AH) + buf * (16 * PA);
            const unsigned* aLb = (const unsigned*)(sm + OFF_AL) + buf * (16 * PA);
            const unsigned* bHb = (const unsigned*)(sm + OFF_BH) + buf * (16 * PB);
            const unsigned* bLb = (const unsigned*)(sm + OFF_BL) + buf * (16 * PB);
#pragma unroll
            for (int kk = 0; kk < 2; kk++) {
                int pl = kk * 8;
                unsigned aH[2][4], aL[2][4];
#pragma unroll
                for (int rt = 0; rt < 2; rt++) {
                    int rb = wr * 32 + rt * 16;
                    aH[rt][0] = aHb[(pl + t) * PA + rb + g];
                    aH[rt][1] = aHb[(pl + t) * PA + rb + g + 8];
                    aH[rt][2] = aHb[(pl + t + 4) * PA + rb + g];
                    aH[rt][3] = aHb[(pl + t + 4) * PA + rb + g + 8];
                    aL[rt][0] = aLb[(pl + t) * PA + rb + g];
                    aL[rt][1] = aLb[(pl + t) * PA + rb + g + 8];
                    aL[rt][2] = aLb[(pl + t + 4) * PA + rb + g];
                    aL[rt][3] = aLb[(pl + t + 4) * PA + rb + g + 8];
                }
#pragma unroll
                for (int ct = 0; ct < 8; ct++) {
                    int cb_ = wc * 64 + ct * 8 + g;
                    unsigned bH0 = bHb[(pl + t) * PB + cb_];
                    unsigned bH1 = bHb[(pl + t + 4) * PB + cb_];
                    unsigned bL0 = bLb[(pl + t) * PB + cb_];
                    unsigned bL1 = bLb[(pl + t + 4) * PB + cb_];
#pragma unroll
                    for (int rt = 0; rt < 2; rt++) {
                        MMA_BF16(acc[rt][ct], aH[rt][0], aH[rt][1], aH[rt][2], aH[rt][3], bH0, bH1);
                        MMA_BF16(acc[rt][ct], aH[rt][0], aH[rt][1], aH[rt][2], aH[rt][3], bL0, bL1);
                        MMA_BF16(acc[rt][ct], aL[rt][0], aL[rt][1], aL[rt][2], aL[rt][3], bH0, bH1);
                    }
                }
            }
            if (c + 1 < C) { WAITB(); __syncthreads(); }
        }
    }

    float* P = g_part + s * (NNODE * DDIM);
#pragma unroll
    for (int rt = 0; rt < 2; rt++) {
        int row = T * TM + wr * 32 + rt * 16 + g;
#pragma unroll
        for (int ct = 0; ct < 8; ct++) {
            int col = wc * 64 + ct * 8 + t * 2;
            *(float2*)&P[row * DDIM + col]       = make_float2(acc[rt][ct][0], acc[rt][ct][1]);
            *(float2*)&P[(row + 8) * DDIM + col] = make_float2(acc[rt][ct][2], acc[rt][ct][3]);
        }
    }
}

__global__ void k_reduce(float* __restrict__ out) {
    int jj = blockIdx.x, i = threadIdx.x;
    int K = g_Kof[jj];
    float sum = g_cb[K][i];
#pragma unroll
    for (int s = 0; s < SST; s++)
        sum += g_part[s * (NNODE * DDIM) + jj * DDIM + i];
    out[g_nodeOf[jj] * DDIM + i] = sum;
}

// ---------------- launch ----------------
extern "C" void kernel_launch(void* const* d_in, const int* in_sizes, int n_in,
                              void* d_out, int out_size) {
    const float* msg = nullptr; const int* idx = nullptr;
    const float* t = nullptr; const float* W = nullptr; const float* b = nullptr;
    int seenE = 0;
    for (int i = 0; i < n_in; i++) {
        long sz = in_sizes[i];
        if (sz == (long)EMSG * DDIM)      msg = (const float*)d_in[i];
        else if (sz == EMSG) {
            if (seenE == 0) idx = (const int*)d_in[i];
            else            t   = (const float*)d_in[i];
            seenE++;
        }
        else if (sz == DDIM * DDIM)       W = (const float*)d_in[i];
        else if (sz == DDIM)              b = (const float*)d_in[i];
    }

    static cudaStream_t s2;
    static cudaEvent_t e0, e1, e2;
    static int cfg = 0;
    if (!cfg) {
        cudaFuncSetAttribute(k_mma, cudaFuncAttributeMaxDynamicSharedMemorySize, SMEM_SZ);
        cudaStreamCreateWithFlags(&s2, cudaStreamNonBlocking);
        cudaEventCreateWithFlags(&e0, cudaEventDisableTiming);
        cudaEventCreateWithFlags(&e1, cudaEventDisableTiming);
        cudaEventCreateWithFlags(&e2, cudaEventDisableTiming);
        cfg = 1;
    }

    // main: init + hist (g_counts ready; g_pmax zeroed)
    k_init<<<32,  256>>>();
    k_hist<<<512, 256>>>(idx);
    cudaEventRecord(e0, 0);

    // fork: W chain on s2 (pmax-gated)
    cudaStreamWaitEvent(s2, e0, 0);
    k_pmax     <<<32,  256, 0, s2>>>();
    k_transpose<<<256, 256, 0, s2>>>(W);
    for (int half = 1; half <= 32; half <<= 1)
        k_wpow<<<dim3(16, half), 256, 0, s2>>>(half);
    k_wsplit<<<dim3(128, PCAP), 256, 0, s2>>>();
    cudaEventRecord(e1, s2);                 // gates k_mma
    k_vj    <<<PCAP - 1, 256, 0, s2>>>(b);
    k_cbias <<<1, 256, 0, s2>>>(b);
    cudaEventRecord(e2, s2);                 // gates k_reduce

    // main: sort chain
    k_scan    <<<1,  1024>>>();
    k_scatter <<<512, 256>>>(idx, t);
    k_kbhist  <<<32,  256>>>();
    k_kscan   <<<1,    NB>>>();
    k_korder  <<<32,  256>>>();
    k_sortgidx<<<1024,256>>>();

    // join
    cudaStreamWaitEvent(0, e1, 0);
    k_mma   <<<NTILE * SST, 512, SMEM_SZ>>>(msg);
    cudaStreamWaitEvent(0, e2, 0);
    k_reduce<<<NNODE, 256>>>((float*)d_out);
}

// round 14
// speedup vs baseline: 1.0723x; 1.0723x over previous
#include <cuda_runtime.h>
#include <cuda_bf16.h>

#define EMSG  131072
#define NNODE 8192
#define DDIM  256
#define NB    512
#define PCAP  64
#define TM    128
#define SST   8
#define NTILE (NNODE/TM)
#define PB    264
#define PA    136

typedef unsigned long long u64;

__device__ int   g_counts [NNODE];
__device__ int   g_offsets[NNODE];
__device__ int   g_cursor [NNODE];
__device__ int   g_ids    [EMSG];
__device__ float g_tk     [EMSG];
__device__ int   g_order  [NNODE];
__device__ int   g_kbins  [NB];
__device__ int   g_koff   [NB];
__device__ int   g_kcur   [NB];
__device__ int   g_pmax;
__device__ int   g_gidx   [PCAP * NNODE];
__device__ int   g_nodeOf [NNODE];
__device__ int   g_Kof    [NNODE];
__device__ __align__(16) float    g_Wp [PCAP][DDIM*DDIM];   // (W^p)^T fp32
__device__ __align__(16) unsigned g_WH [PCAP][128*DDIM];    // bf16x2 hi (k-pair packed)
__device__ __align__(16) unsigned g_WL [PCAP][128*DDIM];    // bf16x2 lo
__device__ __align__(16) float    g_v  [PCAP][DDIM];
__device__ __align__(16) float    g_cb [PCAP+1][DDIM];
__device__ __align__(16) float    g_part[SST * NNODE * DDIM];

__device__ __forceinline__ void split2(float x0, float x1, unsigned& hi, unsigned& lo) {
    __nv_bfloat16 h0 = __float2bfloat16(x0);
    __nv_bfloat16 h1 = __float2bfloat16(x1);
    float r0 = x0 - __bfloat162float(h0);
    float r1 = x1 - __bfloat162float(h1);
    __nv_bfloat162 H; H.x = h0; H.y = h1;
    __nv_bfloat162 L = __floats2bfloat162_rn(r0, r1);
    hi = *(unsigned*)&H; lo = *(unsigned*)&L;
}

#define MMA_BF16(c, A0, A1, A2, A3, B0, B1) \
    asm volatile("mma.sync.aligned.m16n8k16.row.col.f32.bf16.bf16.f32 " \
        "{%0,%1,%2,%3}, {%4,%5,%6,%7}, {%8,%9}, {%0,%1,%2,%3};" \
        : "+f"(c[0]), "+f"(c[1]), "+f"(c[2]), "+f"(c[3]) \
        : "r"(A0), "r"(A1), "r"(A2), "r"(A3), "r"(B0), "r"(B1))

// ---------------- setup ----------------
__global__ void k_init() {
    int i = blockIdx.x * blockDim.x + threadIdx.x;
    if (i < NNODE) { g_counts[i] = 0; g_cursor[i] = 0; }
    if (i < NB)    { g_kbins[i]  = 0; g_kcur[i]   = 0; }
    if (i == 0)    g_pmax = 0;
}
__global__ void k_hist(const int* __restrict__ idx) {
    int e = blockIdx.x * blockDim.x + threadIdx.x;
    if (e < EMSG) atomicAdd(&g_counts[idx[e]], 1);
}
__global__ void k_pmax() {
    __shared__ int sm_;
    if (threadIdx.x == 0) sm_ = 0;
    __syncthreads();
    int n = blockIdx.x * blockDim.x + threadIdx.x;
    int v = (n < NNODE) ? min(g_counts[n], PCAP) : 0;
#pragma unroll
    for (int o = 16; o > 0; o >>= 1) v = max(v, __shfl_down_sync(~0u, v, o));
    if ((threadIdx.x & 31) == 0) atomicMax(&sm_, v);
    __syncthreads();
    if (threadIdx.x == 0) atomicMax(&g_pmax, sm_);
}
__global__ void k_scan() {
    __shared__ int part[1024];
    int tid = threadIdx.x, base = tid * 8;
    int loc[8]; int s = 0;
#pragma unroll
    for (int j = 0; j < 8; j++) { loc[j] = g_counts[base + j]; s += loc[j]; }
    part[tid] = s; __syncthreads();
    for (int off = 1; off < 1024; off <<= 1) {
        int v = (tid >= off) ? part[tid - off] : 0;
        __syncthreads(); part[tid] += v; __syncthreads();
    }
    int run = (tid > 0) ? part[tid - 1] : 0;
#pragma unroll
    for (int j = 0; j < 8; j++) { g_offsets[base + j] = run; run += loc[j]; }
}
__global__ void k_scatter(const int* __restrict__ idx, const float* __restrict__ t) {
    int e = blockIdx.x * blockDim.x + threadIdx.x;
    if (e < EMSG) {
        int n = idx[e];
        int p = atomicAdd(&g_cursor[n], 1);
        int slot = g_offsets[n] + p;
        g_ids[slot] = e; g_tk[slot] = t[e];
    }
}
__global__ void k_kbhist() {
    int n = blockIdx.x * blockDim.x + threadIdx.x;
    if (n < NNODE) atomicAdd(&g_kbins[min(g_counts[n], NB - 1)], 1);
}
__global__ void k_kscan() {
    __shared__ int part[NB];
    int tid = threadIdx.x;
    part[tid] = g_kbins[tid]; __syncthreads();
    for (int off = 1; off < NB; off <<= 1) {
        int v = (tid >= off) ? part[tid - off] : 0;
        __syncthreads(); part[tid] += v; __syncthreads();
    }
    g_koff[tid] = (tid > 0) ? part[tid - 1] : 0;
}
__global__ void k_korder() {
    int n = blockIdx.x * blockDim.x + threadIdx.x;
    if (n < NNODE) {
        int kb = min(g_counts[n], NB - 1);
        int p = atomicAdd(&g_kcur[kb], 1);
        g_order[g_koff[kb] + p] = n;
    }
}
__global__ void k_sortgidx() {
    int wg  = (blockIdx.x * blockDim.x + threadIdx.x) >> 5;
    int lane = threadIdx.x & 31;
    if (wg >= NNODE) return;
    int j = wg;
    int n = g_order[NNODE - 1 - j];
    int K = g_counts[n], off = g_offsets[n];
    int Kc = min(K, PCAP);
    if (lane == 0) { g_nodeOf[j] = n; g_Kof[j] = Kc; }
    u64 v0 = ~0ull, v1 = ~0ull;
    if (lane < K)
        v0 = (((u64)__float_as_uint(g_tk[off + lane])) << 32) | (unsigned)g_ids[off + lane];
    if (lane + 32 < K)
        v1 = (((u64)__float_as_uint(g_tk[off + lane + 32])) << 32) | (unsigned)g_ids[off + lane + 32];
#pragma unroll
    for (int k = 2; k <= 64; k <<= 1) {
#pragma unroll
        for (int jj = k >> 1; jj > 0; jj >>= 1) {
            if (jj == 32) {
                u64 lo = v0 < v1 ? v0 : v1;
                u64 hi = v0 < v1 ? v1 : v0;
                v0 = lo; v1 = hi;
            } else {
                u64 p0 = __shfl_xor_sync(0xffffffffu, v0, jj);
                u64 p1 = __shfl_xor_sync(0xffffffffu, v1, jj);
                bool up  = (lane & jj) == 0;
                bool as0 = (lane & k) == 0;
                bool as1 = ((lane + 32) & k) == 0;
                v0 = (as0 == up) ? (v0 < p0 ? v0 : p0) : (v0 < p0 ? p0 : v0);
                v1 = (as1 == up) ? (v1 < p1 ? v1 : p1) : (v1 < p1 ? p1 : v1);
            }
        }
    }
    if (lane < Kc)
        g_gidx[(Kc - lane - 1) * NNODE + j] = (int)(unsigned)(v0 & 0xffffffffull);
    if (lane + 32 < Kc)
        g_gidx[(Kc - lane - 33) * NNODE + j] = (int)(unsigned)(v1 & 0xffffffffull);
}
__global__ void k_transpose(const float* __restrict__ W) {
    int i = blockIdx.x * blockDim.x + threadIdx.x;
    int k = i >> 8, jj = i & 255;
    g_Wp[0][k * DDIM + jj] = W[jj * DDIM + k];
}

// W powers: 64x64 tile, 4x4 per thread. C = (W^{half+r})^T = (W^r)^T @ (W^half)^T
__global__ void __launch_bounds__(256) k_wpow(int half) {
    int r = blockIdx.y + 1, p = half + r;
    if (p > PCAP || p > g_pmax) return;
    const float4* P4 = (const float4*)g_Wp[r - 1];
    const float4* Q4 = (const float4*)g_Wp[half - 1];
    float* C = g_Wp[p - 1];
    int row0 = (blockIdx.x & 3) * 64;
    int col0 = (blockIdx.x >> 2) * 64;

    __shared__ __align__(16) float sPT[16 * 68];   // [kk][row]
    __shared__ __align__(16) float sQ [16 * 68];   // [kk][col]

    int tid = threadIdx.x;
    int ty = tid >> 4, tx = tid & 15;
    int pr = tid >> 2, pq = tid & 3;     // P: row, k-quad
    int qk = tid >> 4, qc = tid & 15;    // Q: k-row, col-quad
    float acc[4][4] = {};

    for (int kc = 0; kc < DDIM; kc += 16) {
        float4 pv = P4[(row0 + pr) * 64 + (kc >> 2) + pq];
        float4 qv = Q4[(kc + qk) * 64 + (col0 >> 2) + qc];
        __syncthreads();
        sPT[(pq * 4 + 0) * 68 + pr] = pv.x;
        sPT[(pq * 4 + 1) * 68 + pr] = pv.y;
        sPT[(pq * 4 + 2) * 68 + pr] = pv.z;
        sPT[(pq * 4 + 3) * 68 + pr] = pv.w;
        *(float4*)&sQ[qk * 68 + qc * 4] = qv;
        __syncthreads();
#pragma unroll
        for (int kk = 0; kk < 16; kk++) {
            float4 a = *(float4*)&sPT[kk * 68 + ty * 4];
            float4 b = *(float4*)&sQ[kk * 68 + tx * 4];
            float ar[4] = {a.x, a.y, a.z, a.w};
            float br[4] = {b.x, b.y, b.z, b.w};
#pragma unroll
            for (int i = 0; i < 4; i++)
#pragma unroll
                for (int j = 0; j < 4; j++)
                    acc[i][j] += ar[i] * br[j];
        }
    }
#pragma unroll
    for (int i = 0; i < 4; i++)
        *(float4*)&C[(row0 + ty * 4 + i) * DDIM + col0 + tx * 4] =
            make_float4(acc[i][0], acc[i][1], acc[i][2], acc[i][3]);
}

// bf16 hi/lo k-pair packed: g_WH[p][pair*256+j] = {Wt[2k][j], Wt[2k+1][j]}
__global__ void k_wsplit() {
    int p = blockIdx.y;
    if (p >= g_pmax) return;
    int i = blockIdx.x * 256 + threadIdx.x;
    int pair = i >> 8, jj = i & 255;
    const float* Wt = g_Wp[p];
    float x0 = Wt[(2 * pair) * DDIM + jj];
    float x1 = Wt[(2 * pair + 1) * DDIM + jj];
    unsigned h, l; split2(x0, x1, h, l);
    g_WH[p][pair * DDIM + jj] = h;
    g_WL[p][pair * DDIM + jj] = l;
}
__global__ void k_vj(const float* __restrict__ b) {
    int jj = blockIdx.x + 1;
    if (jj >= g_pmax) return;
    __shared__ float sb[DDIM];
    sb[threadIdx.x] = b[threadIdx.x];
    __syncthreads();
    const float* Wt = g_Wp[jj - 1];
    int i = threadIdx.x;
    float s = 0.f;
#pragma unroll 8
    for (int k = 0; k < DDIM; k++) s += Wt[k * DDIM + i] * sb[k];
    g_v[jj][i] = s;
}
__global__ void k_cbias(const float* __restrict__ b) {
    int i = threadIdx.x;
    float run = 0.f;
    g_cb[0][i] = 0.f;
    for (int K = 1; K <= PCAP; K++) {
        run += (K == 1) ? b[i] : g_v[K - 1][i];
        g_cb[K][i] = run;
    }
}

// ---------------- main tensor-core kernel (exact R8/R12: proven 367us path) ----------------
__global__ void __launch_bounds__(512, 1) k_mma(const float* __restrict__ msg) {
    __shared__ __align__(16) unsigned sBH[16 * PB], sBL[16 * PB];
    __shared__ __align__(16) unsigned sAH[16 * PA], sAL[16 * PA];
    __shared__ int sId[TM];

    int T = blockIdx.x >> 3, s = blockIdx.x & 7;
    int tid = threadIdx.x;
    int w = tid >> 5, l = tid & 31;
    int g = l >> 2, t = l & 3;
    int wr = w & 3, wc = w >> 2;
    int Kmax = g_Kof[T * TM];

    float acc[2][8][4];
#pragma unroll
    for (int a = 0; a < 2; a++)
#pragma unroll
        for (int c = 0; c < 8; c++)
#pragma unroll
            for (int q = 0; q < 4; q++) acc[a][c][q] = 0.f;

    const float4* msg4 = (const float4*)msg;
    int arow = tid >> 2, aq = tid & 3;

    for (int p = s + 1; p <= Kmax; p += SST) {
        __syncthreads();
        if (tid < TM) {
            int jj = T * TM + tid;
            sId[tid] = (p <= g_Kof[jj]) ? g_gidx[(p - 1) * NNODE + jj] : -1;
        }
        __syncthreads();
        const unsigned* WH = g_WH[p - 1];
        const unsigned* WL = g_WL[p - 1];
        int aid = sId[arow];

        for (int kc = 0; kc < DDIM; kc += 32) {
            int pb = kc >> 1;
#pragma unroll
            for (int u = 0; u < 2; u++) {
                int f = u * 512 + tid;
                int pr = f >> 6, j4 = f & 63;
                uint4 vH = ((const uint4*)WH)[(pb + pr) * 64 + j4];
                uint4 vL = ((const uint4*)WL)[(pb + pr) * 64 + j4];
                *(uint4*)&sBH[pr * PB + j4 * 4] = vH;
                *(uint4*)&sBL[pr * PB + j4 * 4] = vL;
            }
#pragma unroll
            for (int u = 0; u < 2; u++) {
                int f = aq + u * 4;
                float4 v = make_float4(0.f, 0.f, 0.f, 0.f);
                if (aid >= 0) v = msg4[(size_t)aid * 64 + (kc >> 2) + f];
                unsigned h0, l0, h1, l1;
                split2(v.x, v.y, h0, l0);
                split2(v.z, v.w, h1, l1);
                sAH[(2 * f + 0) * PA + arow] = h0; sAL[(2 * f + 0) * PA + arow] = l0;
                sAH[(2 * f + 1) * PA + arow] = h1; sAL[(2 * f + 1) * PA + arow] = l1;
            }
            __syncthreads();

#pragma unroll
            for (int kk = 0; kk < 2; kk++) {
                int pl = kk * 8;
                unsigned aH[2][4], aL[2][4];
#pragma unroll
                for (int rt = 0; rt < 2; rt++) {
                    int rb = wr * 32 + rt * 16;
                    aH[rt][0] = sAH[(pl + t) * PA + rb + g];
                    aH[rt][1] = sAH[(pl + t) * PA + rb + g + 8];
                    aH[rt][2] = sAH[(pl + t + 4) * PA + rb + g];
                    aH[rt][3] = sAH[(pl + t + 4) * PA + rb + g + 8];
                    aL[rt][0] = sAL[(pl + t) * PA + rb + g];
                    aL[rt][1] = sAL[(pl + t) * PA + rb + g + 8];
                    aL[rt][2] = sAL[(pl + t + 4) * PA + rb + g];
                    aL[rt][3] = sAL[(pl + t + 4) * PA + rb + g + 8];
                }
#pragma unroll
                for (int ct = 0; ct < 8; ct++) {
                    int cb_ = wc * 64 + ct * 8 + g;
                    unsigned bH0 = sBH[(pl + t) * PB + cb_];
                    unsigned bH1 = sBH[(pl + t + 4) * PB + cb_];
                    unsigned bL0 = sBL[(pl + t) * PB + cb_];
                    unsigned bL1 = sBL[(pl + t + 4) * PB + cb_];
#pragma unroll
                    for (int rt = 0; rt < 2; rt++) {
                        MMA_BF16(acc[rt][ct], aH[rt][0], aH[rt][1], aH[rt][2], aH[rt][3], bH0, bH1);
                        MMA_BF16(acc[rt][ct], aH[rt][0], aH[rt][1], aH[rt][2], aH[rt][3], bL0, bL1);
                        MMA_BF16(acc[rt][ct], aL[rt][0], aL[rt][1], aL[rt][2], aL[rt][3], bH0, bH1);
                    }
                }
            }
            __syncthreads();
        }
    }

    float* P = g_part + s * (NNODE * DDIM);
#pragma unroll
    for (int rt = 0; rt < 2; rt++) {
        int row = T * TM + wr * 32 + rt * 16 + g;
#pragma unroll
        for (int ct = 0; ct < 8; ct++) {
            int col = wc * 64 + ct * 8 + t * 2;
            *(float2*)&P[row * DDIM + col]       = make_float2(acc[rt][ct][0], acc[rt][ct][1]);
            *(float2*)&P[(row + 8) * DDIM + col] = make_float2(acc[rt][ct][2], acc[rt][ct][3]);
        }
    }
}

__global__ void k_reduce(float* __restrict__ out) {
    int jj = blockIdx.x, i = threadIdx.x;
    int K = g_Kof[jj];
    float sum = g_cb[K][i];
#pragma unroll
    for (int s = 0; s < SST; s++)
        sum += g_part[s * (NNODE * DDIM) + jj * DDIM + i];
    out[g_nodeOf[jj] * DDIM + i] = sum;
}

// ---------------- launch: W chain forked after hist (pmax-gated) ----------------
extern "C" void kernel_launch(void* const* d_in, const int* in_sizes, int n_in,
                              void* d_out, int out_size) {
    const float* msg = nullptr; const int* idx = nullptr;
    const float* t = nullptr; const float* W = nullptr; const float* b = nullptr;
    int seenE = 0;
    for (int i = 0; i < n_in; i++) {
        long sz = in_sizes[i];
        if (sz == (long)EMSG * DDIM)      msg = (const float*)d_in[i];
        else if (sz == EMSG) {
            if (seenE == 0) idx = (const int*)d_in[i];
            else            t   = (const float*)d_in[i];
            seenE++;
        }
        else if (sz == DDIM * DDIM)       W = (const float*)d_in[i];
        else if (sz == DDIM)              b = (const float*)d_in[i];
    }

    static cudaStream_t s2;
    static cudaEvent_t e0, e1, e2;
    static int cfg = 0;
    if (!cfg) {
        cudaStreamCreateWithFlags(&s2, cudaStreamNonBlocking);
        cudaEventCreateWithFlags(&e0, cudaEventDisableTiming);
        cudaEventCreateWithFlags(&e1, cudaEventDisableTiming);
        cudaEventCreateWithFlags(&e2, cudaEventDisableTiming);
        cfg = 1;
    }

    // main: init + hist (g_counts ready; g_pmax zeroed)
    k_init<<<32,  256>>>();
    k_hist<<<512, 256>>>(idx);
    cudaEventRecord(e0, 0);

    // fork: W chain on s2 (pmax-gated)
    cudaStreamWaitEvent(s2, e0, 0);
    k_pmax     <<<32,  256, 0, s2>>>();
    k_transpose<<<256, 256, 0, s2>>>(W);
    for (int half = 1; half <= 32; half <<= 1)
        k_wpow<<<dim3(16, half), 256, 0, s2>>>(half);
    k_wsplit<<<dim3(128, PCAP), 256, 0, s2>>>();
    cudaEventRecord(e1, s2);                 // gates k_mma
    k_vj    <<<PCAP - 1, 256, 0, s2>>>(b);
    k_cbias <<<1, 256, 0, s2>>>(b);
    cudaEventRecord(e2, s2);                 // gates k_reduce

    // main: sort chain
    k_scan    <<<1,  1024>>>();
    k_scatter <<<512, 256>>>(idx, t);
    k_kbhist  <<<32,  256>>>();
    k_kscan   <<<1,    NB>>>();
    k_korder  <<<32,  256>>>();
    k_sortgidx<<<1024,256>>>();

    // join
    cudaStreamWaitEvent(0, e1, 0);
    k_mma   <<<NTILE * SST, 512>>>(msg);
    cudaStreamWaitEvent(0, e2, 0);
    k_reduce<<<NNODE, 256>>>((float*)d_out);
}